// round 4
// baseline (speedup 1.0000x reference)
#include <cuda_runtime.h>
#include <math.h>

#define NN      100000   // nodes
#define HID     64
#define NL      40

// ---------------- scratch (no allocations allowed) ----------------
// __align__(256): red.global.add.v4.f32 requires 16B-aligned addresses.
__device__ __align__(256) float g_h [NN * HID];   // layer-1 pre-propagation activations
__device__ __align__(256) float g_h2[NN * HID];   // propagated (pre-relu) activations
__device__ __align__(256) float g_z [NN * NL];    // dense-layer output

// vector reduction (no-return atomic), sm_90+
__device__ __forceinline__ void red_add_v4(float* p, float a, float b, float c, float d) {
    asm volatile("red.global.add.v4.f32 [%0], {%1,%2,%3,%4};"
                 :: "l"(p), "f"(a), "f"(b), "f"(c), "f"(d) : "memory");
}

// ---------------- kernels ----------------

// h = b1 (broadcast), h2 = 0, d_out = 0
__global__ void k_init(const float* __restrict__ b1, float* __restrict__ out) {
    int i = blockIdx.x * blockDim.x + threadIdx.x;
    if (i < NN * HID) {
        g_h [i] = b1[i & (HID - 1)];
        g_h2[i] = 0.0f;
    }
    if (i < NN * NL) out[i] = 0.0f;
}

// h += features @ W1   (COO scatter, 16 float4-lanes per nnz)
__global__ void k_feat_spmm(const int* __restrict__ frow,
                            const int* __restrict__ fcol,
                            const float* __restrict__ fval,
                            const float* __restrict__ W1, int nnz) {
    long long tid = (long long)blockIdx.x * blockDim.x + threadIdx.x;
    int k = (int)(tid >> 4);
    int j = (int)(tid & 15);
    if (k >= nnz) return;
    int   r = frow[k];
    int   c = fcol[k];
    float v = fval[k];
    float4 w = reinterpret_cast<const float4*>(W1 + (size_t)c * HID)[j];
    red_add_v4(g_h + (size_t)r * HID + 4 * j, v * w.x, v * w.y, v * w.z, v * w.w);
}

// h2 += A_norm @ h   (COO scatter over edges, 16 float4-lanes per edge)
__global__ void k_edge_spmm_h(const int* __restrict__ erow,
                              const int* __restrict__ ecol,
                              const float* __restrict__ ew, int ne) {
    long long tid = (long long)blockIdx.x * blockDim.x + threadIdx.x;
    int k = (int)(tid >> 4);
    int j = (int)(tid & 15);
    if (k >= ne) return;
    int   r = erow[k];
    int   c = ecol[k];
    float w = ew[k];
    float4 hv = reinterpret_cast<const float4*>(g_h + (size_t)c * HID)[j];
    red_add_v4(g_h2 + (size_t)r * HID + 4 * j, w * hv.x, w * hv.y, w * hv.z, w * hv.w);
}

// z = relu(h2) @ W2 + b2   (one thread per node; W2/b2 in shared)
__global__ void k_dense(const float* __restrict__ W2, const float* __restrict__ b2) {
    __shared__ float sW[HID * NL];
    __shared__ float sb[NL];
    for (int i = threadIdx.x; i < HID * NL; i += blockDim.x) sW[i] = W2[i];
    if (threadIdx.x < NL) sb[threadIdx.x] = b2[threadIdx.x];
    __syncthreads();

    int node = blockIdx.x * blockDim.x + threadIdx.x;
    if (node >= NN) return;

    float acc[NL];
#pragma unroll
    for (int j = 0; j < NL; j++) acc[j] = sb[j];

    const float4* hrow = reinterpret_cast<const float4*>(g_h2 + (size_t)node * HID);
#pragma unroll
    for (int t4 = 0; t4 < HID / 4; t4++) {
        float4 h4 = hrow[t4];
        float hv[4] = {fmaxf(h4.x, 0.f), fmaxf(h4.y, 0.f), fmaxf(h4.z, 0.f), fmaxf(h4.w, 0.f)};
#pragma unroll
        for (int u = 0; u < 4; u++) {
            int t = t4 * 4 + u;
#pragma unroll
            for (int j = 0; j < NL; j++) acc[j] += hv[u] * sW[t * NL + j];
        }
    }
    float* zrow = g_z + (size_t)node * NL;
#pragma unroll
    for (int j = 0; j < NL; j++) zrow[j] = acc[j];
}

// out += A_norm @ z   (10 float4-lanes per edge)
__global__ void k_z_spmm(const int* __restrict__ erow,
                         const int* __restrict__ ecol,
                         const float* __restrict__ ew,
                         float* __restrict__ out, int ne) {
    long long tid = (long long)blockIdx.x * blockDim.x + threadIdx.x;
    int k = (int)(tid / 10);
    int j = (int)(tid - (long long)k * 10);
    if (k >= ne) return;
    int   r = erow[k];
    int   c = ecol[k];
    float w = ew[k];
    float4 zv = reinterpret_cast<const float4*>(g_z + (size_t)c * NL)[j];
    red_add_v4(out + (size_t)r * NL + 4 * j, w * zv.x, w * zv.y, w * zv.z, w * zv.w);
}

// in-place log_softmax over rows of 40; one warp per node
__global__ void k_logsoftmax(float* __restrict__ out) {
    int gwarp = (blockIdx.x * blockDim.x + threadIdx.x) >> 5;
    int lane  = threadIdx.x & 31;
    if (gwarp >= NN) return;
    float* row = out + (size_t)gwarp * NL;

    float v0 = row[lane];
    float v1 = (lane < NL - 32) ? row[32 + lane] : -1e30f;

    float m = fmaxf(v0, v1);
#pragma unroll
    for (int o = 16; o > 0; o >>= 1) m = fmaxf(m, __shfl_xor_sync(0xffffffffu, m, o));

    float s = __expf(v0 - m) + ((lane < NL - 32) ? __expf(v1 - m) : 0.0f);
#pragma unroll
    for (int o = 16; o > 0; o >>= 1) s += __shfl_xor_sync(0xffffffffu, s, o);

    float l = m + logf(s);
    row[lane] = v0 - l;
    if (lane < NL - 32) row[32 + lane] = v1 - l;
}

// ---------------- launch ----------------
extern "C" void kernel_launch(void* const* d_in, const int* in_sizes, int n_in,
                              void* d_out, int out_size) {
    const int*   fidx = (const int*)  d_in[0];   // int32 (JAX x64 disabled)
    const float* fval = (const float*)d_in[1];
    const int*   eidx = (const int*)  d_in[2];   // int32
    const float* ew   = (const float*)d_in[3];
    const float* W1   = (const float*)d_in[4];
    const float* b1   = (const float*)d_in[5];
    const float* W2   = (const float*)d_in[6];
    const float* b2   = (const float*)d_in[7];
    float* out = (float*)d_out;

    int nnz = in_sizes[0] / 2;        // feature_indices is [2, NNZ]
    int ne  = in_sizes[2] / 2;        // edge_indices is [2, E]

    const int* frow = fidx;
    const int* fcol = fidx + nnz;
    const int* erow = eidx;
    const int* ecol = eidx + ne;

    // 1. init scratch + zero output
    {
        int lanes = NN * HID;
        k_init<<<(lanes + 255) / 256, 256>>>(b1, out);
    }
    // 2. feature SpMM -> g_h
    {
        long long lanes = (long long)nnz * 16;
        k_feat_spmm<<<(unsigned)((lanes + 255) / 256), 256>>>(frow, fcol, fval, W1, nnz);
    }
    // 3. adjacency SpMM -> g_h2
    {
        long long lanes = (long long)ne * 16;
        k_edge_spmm_h<<<(unsigned)((lanes + 255) / 256), 256>>>(erow, ecol, ew, ne);
    }
    // 4. dense layer (relu fused on read) -> g_z
    {
        k_dense<<<(NN + 127) / 128, 128>>>(W2, b2);
    }
    // 5. adjacency SpMM -> out
    {
        long long lanes = (long long)ne * 10;
        k_z_spmm<<<(unsigned)((lanes + 255) / 256), 256>>>(erow, ecol, ew, out, ne);
    }
    // 6. log-softmax in place
    {
        int threads = 256;                      // 8 warps/block
        int blocks  = (NN + 7) / 8;
        k_logsoftmax<<<blocks, threads>>>(out);
    }
}

// round 5
// speedup vs baseline: 1.2307x; 1.2307x over previous
#include <cuda_runtime.h>
#include <math.h>

#define NN      100000   // nodes
#define HID     64
#define NL      40
#define NNZ_MAX 2500000  // feature nonzeros
#define NE_MAX  1700000  // edges incl self loops
#define SCAN_N  (2 * NN)          // concatenated f/e count array
#define SCAN_B  ((SCAN_N + 1023) / 1024)

// ---------------- scratch (no allocations allowed) ----------------
__device__ __align__(256) float g_h [NN * HID];   // layer-1 activations
__device__ __align__(256) float g_h2[NN * HID];   // propagated activations
__device__ __align__(256) float g_z [NN * NL];    // dense-layer output

__device__ int  g_cnt[SCAN_N];        // per-row counts (f rows | e rows)
__device__ int  g_off[SCAN_N + 1];    // exclusive offsets (concatenated)
__device__ int  g_cur[SCAN_N];        // fill cursors
__device__ int  g_bsum[256];          // scan block sums
__device__ __align__(16) int2 g_fcv[NNZ_MAX];  // (col, val-bits) feature CSR
__device__ __align__(16) int2 g_ecv[NE_MAX];   // (col, weight-bits) edge CSR

// ---------------- CSR build ----------------

__global__ void k_zero_cnt() {
    int i = blockIdx.x * blockDim.x + threadIdx.x;
    if (i < SCAN_N) g_cnt[i] = 0;
}

__global__ void k_count(const int* __restrict__ frow, const int* __restrict__ erow,
                        int nnz, int ne) {
    int i = blockIdx.x * blockDim.x + threadIdx.x;
    if (i < nnz)            atomicAdd(&g_cnt[frow[i]], 1);
    else if (i < nnz + ne)  atomicAdd(&g_cnt[NN + erow[i - nnz]], 1);
}

// per-block inclusive scan -> exclusive partials + block totals
__global__ void k_scan1() {
    __shared__ int s[2][1024];
    int tid = threadIdx.x;
    int gid = blockIdx.x * 1024 + tid;
    int v = (gid < SCAN_N) ? g_cnt[gid] : 0;
    int buf = 0;
    s[0][tid] = v; __syncthreads();
#pragma unroll
    for (int o = 1; o < 1024; o <<= 1) {
        int nb = buf ^ 1;
        s[nb][tid] = s[buf][tid] + (tid >= o ? s[buf][tid - o] : 0);
        buf = nb; __syncthreads();
    }
    if (gid < SCAN_N) g_off[gid] = s[buf][tid] - v;   // exclusive within block
    if (tid == 1023) g_bsum[blockIdx.x] = s[buf][1023];
}

// scan the block totals (single block)
__global__ void k_scan2() {
    __shared__ int s[2][256];
    int tid = threadIdx.x;
    int v = (tid < SCAN_B) ? g_bsum[tid] : 0;
    int buf = 0;
    s[0][tid] = v; __syncthreads();
#pragma unroll
    for (int o = 1; o < 256; o <<= 1) {
        int nb = buf ^ 1;
        s[nb][tid] = s[buf][tid] + (tid >= o ? s[buf][tid - o] : 0);
        buf = nb; __syncthreads();
    }
    g_bsum[tid] = s[buf][tid] - v;                    // exclusive
}

__global__ void k_scan3(int total) {
    int gid = blockIdx.x * blockDim.x + threadIdx.x;
    if (gid < SCAN_N) {
        int o = g_off[gid] + g_bsum[gid >> 10];
        g_off[gid] = o;
        g_cur[gid] = o;
    }
    if (gid == 0) g_off[SCAN_N] = total;
}

__global__ void k_fill(const int* __restrict__ frow, const int* __restrict__ fcol,
                       const float* __restrict__ fval,
                       const int* __restrict__ erow, const int* __restrict__ ecol,
                       const float* __restrict__ ew, int nnz, int ne) {
    int i = blockIdx.x * blockDim.x + threadIdx.x;
    if (i < nnz) {
        int r = frow[i];
        int pos = atomicAdd(&g_cur[r], 1);
        g_fcv[pos] = make_int2(fcol[i], __float_as_int(fval[i]));
    } else if (i < nnz + ne) {
        int k = i - nnz;
        int r = erow[k];
        int pos = atomicAdd(&g_cur[NN + r], 1) - nnz;
        g_ecv[pos] = make_int2(ecol[k], __float_as_int(ew[k]));
    }
}

// ---------------- gather SpMMs ----------------

// h[row] = b1 + sum_p val_p * W1[col_p]   (warp per row, float2 per lane)
__global__ void k_feat_gather(const float* __restrict__ W1, const float* __restrict__ b1) {
    int gid = blockIdx.x * blockDim.x + threadIdx.x;
    int row = gid >> 5;
    int lane = threadIdx.x & 31;
    if (row >= NN) return;
    int beg = g_off[row], end = g_off[row + 1];   // g_off[NN] == nnz
    float2 acc = reinterpret_cast<const float2*>(b1)[lane];
#pragma unroll 2
    for (int p = beg; p < end; p++) {
        int2 cv = g_fcv[p];
        float v = __int_as_float(cv.y);
        float2 w = *reinterpret_cast<const float2*>(W1 + (size_t)cv.x * HID + 2 * lane);
        acc.x += v * w.x;
        acc.y += v * w.y;
    }
    *reinterpret_cast<float2*>(g_h + (size_t)row * HID + 2 * lane) = acc;
}

// h2[row] = sum_p w_p * h[col_p]   (warp per row, float2 per lane)
__global__ void k_edge_gather(int nnz) {
    int gid = blockIdx.x * blockDim.x + threadIdx.x;
    int row = gid >> 5;
    int lane = threadIdx.x & 31;
    if (row >= NN) return;
    int beg = g_off[NN + row] - nnz;
    int end = g_off[NN + row + 1] - nnz;
    float2 acc = make_float2(0.f, 0.f);
#pragma unroll 2
    for (int p = beg; p < end; p++) {
        int2 cv = g_ecv[p];
        float w = __int_as_float(cv.y);
        float2 h = *reinterpret_cast<const float2*>(g_h + (size_t)cv.x * HID + 2 * lane);
        acc.x += w * h.x;
        acc.y += w * h.y;
    }
    *reinterpret_cast<float2*>(g_h2 + (size_t)row * HID + 2 * lane) = acc;
}

// z = relu(h2) @ W2 + b2   (one thread per node; W2 in shared as float4)
__global__ void __launch_bounds__(256) k_dense(const float* __restrict__ W2,
                                               const float* __restrict__ b2) {
    __shared__ float4 sW[HID * NL / 4];   // [t][j4], t<64, j4<10 (W2 row-major)
    __shared__ float  sb[NL];
    for (int i = threadIdx.x; i < HID * NL / 4; i += blockDim.x)
        sW[i] = reinterpret_cast<const float4*>(W2)[i];
    if (threadIdx.x < NL) sb[threadIdx.x] = b2[threadIdx.x];
    __syncthreads();

    int node = blockIdx.x * blockDim.x + threadIdx.x;
    if (node >= NN) return;

    float acc[NL];
#pragma unroll
    for (int j = 0; j < NL; j++) acc[j] = sb[j];

    const float4* hrow = reinterpret_cast<const float4*>(g_h2 + (size_t)node * HID);
#pragma unroll
    for (int t4 = 0; t4 < HID / 4; t4++) {
        float4 h4 = hrow[t4];
        float hv[4] = {fmaxf(h4.x, 0.f), fmaxf(h4.y, 0.f), fmaxf(h4.z, 0.f), fmaxf(h4.w, 0.f)};
#pragma unroll
        for (int u = 0; u < 4; u++) {
            int t = t4 * 4 + u;
#pragma unroll
            for (int j4 = 0; j4 < NL / 4; j4++) {
                float4 w = sW[t * (NL / 4) + j4];
                acc[4 * j4 + 0] += hv[u] * w.x;
                acc[4 * j4 + 1] += hv[u] * w.y;
                acc[4 * j4 + 2] += hv[u] * w.z;
                acc[4 * j4 + 3] += hv[u] * w.w;
            }
        }
    }
    float* zrow = g_z + (size_t)node * NL;
#pragma unroll
    for (int j4 = 0; j4 < NL / 4; j4++)
        reinterpret_cast<float4*>(zrow)[j4] =
            make_float4(acc[4*j4], acc[4*j4+1], acc[4*j4+2], acc[4*j4+3]);
}

// out[row] = sum_p w_p * z[col_p]   (40-thread group per row)
__global__ void k_z_gather(float* __restrict__ out, int nnz) {
    int row = blockIdx.x * 8 + threadIdx.x / NL;
    int j   = threadIdx.x % NL;
    if (row >= NN) return;
    int beg = g_off[NN + row] - nnz;
    int end = g_off[NN + row + 1] - nnz;
    float acc = 0.f;
#pragma unroll 2
    for (int p = beg; p < end; p++) {
        int2 cv = g_ecv[p];
        float w = __int_as_float(cv.y);
        acc += w * g_z[(size_t)cv.x * NL + j];
    }
    out[(size_t)row * NL + j] = acc;
}

// in-place log_softmax over rows of 40; one warp per node
__global__ void k_logsoftmax(float* __restrict__ out) {
    int gwarp = (blockIdx.x * blockDim.x + threadIdx.x) >> 5;
    int lane  = threadIdx.x & 31;
    if (gwarp >= NN) return;
    float* row = out + (size_t)gwarp * NL;

    float v0 = row[lane];
    float v1 = (lane < NL - 32) ? row[32 + lane] : -1e30f;

    float m = fmaxf(v0, v1);
#pragma unroll
    for (int o = 16; o > 0; o >>= 1) m = fmaxf(m, __shfl_xor_sync(0xffffffffu, m, o));

    float s = __expf(v0 - m) + ((lane < NL - 32) ? __expf(v1 - m) : 0.0f);
#pragma unroll
    for (int o = 16; o > 0; o >>= 1) s += __shfl_xor_sync(0xffffffffu, s, o);

    float l = m + logf(s);
    row[lane] = v0 - l;
    if (lane < NL - 32) row[32 + lane] = v1 - l;
}

// ---------------- launch ----------------
extern "C" void kernel_launch(void* const* d_in, const int* in_sizes, int n_in,
                              void* d_out, int out_size) {
    const int*   fidx = (const int*)  d_in[0];   // int32
    const float* fval = (const float*)d_in[1];
    const int*   eidx = (const int*)  d_in[2];   // int32
    const float* ew   = (const float*)d_in[3];
    const float* W1   = (const float*)d_in[4];
    const float* b1   = (const float*)d_in[5];
    const float* W2   = (const float*)d_in[6];
    const float* b2   = (const float*)d_in[7];
    float* out = (float*)d_out;

    int nnz = in_sizes[0] / 2;   // feature_indices is [2, NNZ]
    int ne  = in_sizes[2] / 2;   // edge_indices is [2, E]

    const int* frow = fidx;
    const int* fcol = fidx + nnz;
    const int* erow = eidx;
    const int* ecol = eidx + ne;

    int tot = nnz + ne;

    // --- CSR build ---
    k_zero_cnt<<<(SCAN_N + 255) / 256, 256>>>();
    k_count<<<(tot + 255) / 256, 256>>>(frow, erow, nnz, ne);
    k_scan1<<<SCAN_B, 1024>>>();
    k_scan2<<<1, 256>>>();
    k_scan3<<<(SCAN_N + 255) / 256, 256>>>(tot);
    k_fill<<<(tot + 255) / 256, 256>>>(frow, fcol, fval, erow, ecol, ew, nnz, ne);

    // --- forward pass ---
    k_feat_gather<<<(NN * 32 + 255) / 256, 256>>>(W1, b1);
    k_edge_gather<<<(NN * 32 + 255) / 256, 256>>>(nnz);
    k_dense<<<(NN + 255) / 256, 256>>>(W2, b2);
    k_z_gather<<<(NN + 7) / 8, 8 * NL>>>(out, nnz);
    k_logsoftmax<<<(NN + 7) / 8, 256>>>(out);
}